// round 17
// baseline (speedup 1.0000x reference)
#include <cuda_runtime.h>
#include <cuda_fp16.h>
#include <math.h>
#include <stdint.h>

#define T_DIM 4096
#define D_DIM 1024
#define NH    16
#define HD    64
#define L_ROT 32

// Scratch (no allocations allowed -> __device__ globals)
__device__ __half g_Q[NH * T_DIM * HD];
__device__ __half g_K[NH * T_DIM * HD];
__device__ __half g_V[NH * T_DIM * HD];
__device__ float  g_vals[T_DIM * D_DIM];

// ---------------------------------------------------------------------------
// helpers
// ---------------------------------------------------------------------------
__device__ __forceinline__ uint32_t smem_u32(const void* p) {
    uint32_t a;
    asm("{ .reg .u64 t; cvta.to.shared.u64 t, %1; cvt.u32.u64 %0, t; }" : "=r"(a) : "l"(p));
    return a;
}

__device__ __forceinline__ unsigned h2u(__half2 h) { return *(unsigned*)&h; }

// D += A(16x16, row) * B(16x8, col);  f16 in, f32 accum
__device__ __forceinline__ void mma16(float* d, const unsigned* a, unsigned b0, unsigned b1) {
    asm volatile(
        "mma.sync.aligned.m16n8k16.row.col.f32.f16.f16.f32 "
        "{%0,%1,%2,%3}, {%4,%5,%6,%7}, {%8,%9}, {%0,%1,%2,%3};"
        : "+f"(d[0]), "+f"(d[1]), "+f"(d[2]), "+f"(d[3])
        : "r"(a[0]), "r"(a[1]), "r"(a[2]), "r"(a[3]), "r"(b0), "r"(b1));
}

__device__ __forceinline__ void ldm_x4(unsigned* r, uint32_t addr) {
    asm volatile("ldmatrix.sync.aligned.m8n8.x4.shared.b16 {%0,%1,%2,%3}, [%4];"
                 : "=r"(r[0]), "=r"(r[1]), "=r"(r[2]), "=r"(r[3]) : "r"(addr));
}

#define CP_ASYNC16(dst_u32, src_ptr) \
    asm volatile("cp.async.cg.shared.global [%0], [%1], 16;" :: "r"(dst_u32), "l"(src_ptr))
#define CP_COMMIT() asm volatile("cp.async.commit_group;" ::: "memory")

// ---------------------------------------------------------------------------
// fp16 GEMM via mma.sync m16n8k16 + ldmatrix fragment loads.
// C = A (MxK row-major, f32) * B^T (B is NxK row-major, f32)
// mode 0: C[m*N + n] (fp32) ; mode 1: per-head __half layout
// BM=BN=128, BK=32, 256 threads, warp grid 2(M)x4(N), warp tile 64x32.
// ---------------------------------------------------------------------------
#define GAPAD 40    // halves per row (80 B) -> ldmatrix conflict-free

__global__ __launch_bounds__(256) void gemm_f16(
    const float* __restrict__ A, const float* __restrict__ B,
    void* __restrict__ Cout, int M, int N, int K, int mode)
{
    __shared__ __half As[2][128 * GAPAD];
    __shared__ __half Bs[2][128 * GAPAD];

    const int tid = threadIdx.x;
    const int bm = blockIdx.y * 128;
    const int bn = blockIdx.x * 128;
    const int w = tid >> 5, lane = tid & 31;
    const int g = lane >> 2, tg = lane & 3;
    const int wm = (w >> 2) * 64;
    const int wn = (w & 3) * 32;

    const int lr = tid >> 1;
    const int lc = (tid & 1) * 16;

    const float* arow = A + (size_t)(bm + lr) * K + lc;
    const float* brow = B + (size_t)(bn + lr) * K + lc;

    // ldmatrix per-lane byte offsets (within a buffer)
    //   A matrices: rows wm+mt*16+(lane&15), col-half (lane>>4)*8
    //   B matrices: rows wn+ntp*16+((lane>>4)*8)+(lane&7), col-half ((lane>>3)&1)*8
    uint32_t a_off[4], b_off[2];
#pragma unroll
    for (int mt = 0; mt < 4; mt++)
        a_off[mt] = (uint32_t)((wm + mt * 16 + (lane & 15)) * GAPAD + (lane >> 4) * 8) * 2;
#pragma unroll
    for (int ntp = 0; ntp < 2; ntp++)
        b_off[ntp] = (uint32_t)((wn + ntp * 16 + ((lane >> 4) * 8) + (lane & 7)) * GAPAD
                                + ((lane >> 3) & 1) * 8) * 2;
    const uint32_t as_base[2] = { smem_u32(As[0]), smem_u32(As[1]) };
    const uint32_t bs_base[2] = { smem_u32(Bs[0]), smem_u32(Bs[1]) };

    float cf[4][4][4];
#pragma unroll
    for (int mt = 0; mt < 4; mt++)
#pragma unroll
        for (int nt = 0; nt < 4; nt++)
#pragma unroll
            for (int r = 0; r < 4; r++) cf[mt][nt][r] = 0.f;

    float4 av[4], bv[4];
#pragma unroll
    for (int s2 = 0; s2 < 4; s2++) {
        av[s2] = *(const float4*)(arow + s2 * 4);
        bv[s2] = *(const float4*)(brow + s2 * 4);
    }

    const int NC = K / 32;
    for (int c = 0; c < NC; c++) {
        const int buf = c & 1;
        {
            __half2 ah[8], bh[8];
#pragma unroll
            for (int s2 = 0; s2 < 4; s2++) {
                ah[2 * s2]     = __floats2half2_rn(av[s2].x, av[s2].y);
                ah[2 * s2 + 1] = __floats2half2_rn(av[s2].z, av[s2].w);
                bh[2 * s2]     = __floats2half2_rn(bv[s2].x, bv[s2].y);
                bh[2 * s2 + 1] = __floats2half2_rn(bv[s2].z, bv[s2].w);
            }
            *(uint4*)&As[buf][lr * GAPAD + lc]     = *(uint4*)&ah[0];
            *(uint4*)&As[buf][lr * GAPAD + lc + 8] = *(uint4*)&ah[4];
            *(uint4*)&Bs[buf][lr * GAPAD + lc]     = *(uint4*)&bh[0];
            *(uint4*)&Bs[buf][lr * GAPAD + lc + 8] = *(uint4*)&bh[4];
        }
        if (c + 1 < NC) {
            const float* ap = arow + (c + 1) * 32;
            const float* bp = brow + (c + 1) * 32;
#pragma unroll
            for (int s2 = 0; s2 < 4; s2++) {
                av[s2] = *(const float4*)(ap + s2 * 4);
                bv[s2] = *(const float4*)(bp + s2 * 4);
            }
        }
        __syncthreads();

#pragma unroll
        for (int s = 0; s < 2; s++) {
            unsigned af[4][4];
#pragma unroll
            for (int mt = 0; mt < 4; mt++)
                ldm_x4(af[mt], as_base[buf] + a_off[mt] + s * 32);
#pragma unroll
            for (int ntp = 0; ntp < 2; ntp++) {
                unsigned bb[4];
                ldm_x4(bb, bs_base[buf] + b_off[ntp] + s * 32);
#pragma unroll
                for (int mt = 0; mt < 4; mt++) mma16(cf[mt][2 * ntp], af[mt], bb[0], bb[1]);
#pragma unroll
                for (int mt = 0; mt < 4; mt++) mma16(cf[mt][2 * ntp + 1], af[mt], bb[2], bb[3]);
            }
        }
        __syncthreads();
    }

#pragma unroll
    for (int mt = 0; mt < 4; mt++) {
        int m = bm + wm + mt * 16 + g;
#pragma unroll
        for (int nt = 0; nt < 4; nt++) {
            int n = bn + wn + nt * 8 + 2 * tg;
            if (mode == 0) {
                float* C = (float*)Cout;
                *(float2*)&C[(size_t)m * N + n] =
                    make_float2(cf[mt][nt][0], cf[mt][nt][1]);
                *(float2*)&C[(size_t)(m + 8) * N + n] =
                    make_float2(cf[mt][nt][2], cf[mt][nt][3]);
            } else {
                __half* C = (__half*)Cout;
                int h = n >> 6, d = n & 63;
                *(__half2*)&C[(size_t)(h * M + m) * 64 + d] =
                    __floats2half2_rn(cf[mt][nt][0], cf[mt][nt][1]);
                *(__half2*)&C[(size_t)(h * M + m + 8) * 64 + d] =
                    __floats2half2_rn(cf[mt][nt][2], cf[mt][nt][3]);
            }
        }
    }
}

// ---------------------------------------------------------------------------
// fused RoPE on half buffers: first 32 dims of each head (ROT_SCALE = 1)
// ---------------------------------------------------------------------------
__global__ void rope_kernel(__half* __restrict__ bq, __half* __restrict__ bk,
                            __half* __restrict__ bv, const float* __restrict__ freqs)
{
    int idx = blockIdx.x * blockDim.x + threadIdx.x;
    int p = idx & 15;
    int t = (idx >> 4) & (T_DIM - 1);
    int h = idx >> 16;
    if (h >= NH) return;
    __half* buf = (blockIdx.y == 0) ? bq : (blockIdx.y == 1) ? bk : bv;
    __half* x = buf + ((size_t)h * T_DIM + t) * HD;
    float a = __half2float(x[p]);
    float b = __half2float(x[p + 16]);
    float f0 = freqs[t * L_ROT + p];
    float f1 = freqs[t * L_ROT + p + 16];
    x[p]      = __float2half_rn(a * cosf(f0) - b * sinf(f0));
    x[p + 16] = __float2half_rn(b * cosf(f1) + a * sinf(f1));
}

// ---------------------------------------------------------------------------
// Flash attention, fp16 mma, register-resident softmax + ldmatrix B-frags.
// Block = 128 threads (4 warps), 64 q rows; warp w owns rows [16w,16w+16).
// K [j][64] pad 72, V^T [c][j] pad 72 -> ldmatrix conflict-free.
// ---------------------------------------------------------------------------
#define KPADH 72

__global__ __launch_bounds__(128) void attn_mma(
    const __half* __restrict__ Qb, const __half* __restrict__ Kb,
    const __half* __restrict__ Vb, float* __restrict__ vals)
{
    __shared__ __half Ks[2][64 * KPADH];
    __shared__ __half Vs[2][64 * KPADH];   // V transposed: [c][j]

    const int h = blockIdx.y;
    const int it = gridDim.x - 1 - blockIdx.x;   // heavy blocks first
    const int tid = threadIdx.x;
    const int w = tid >> 5, lane = tid & 31;
    const int g = lane >> 2, tg = lane & 3;
    const int stripe = w * 16;

    // ldmatrix per-lane byte offset: rows ntp*16+((lane>>4)*8)+(lane&7),
    // col-half ((lane>>3)&1)*8 ; +s*32 B per k-step of 16
    uint32_t bm_off[4];
#pragma unroll
    for (int ntp = 0; ntp < 4; ntp++)
        bm_off[ntp] = (uint32_t)((ntp * 16 + ((lane >> 4) * 8) + (lane & 7)) * KPADH
                                 + ((lane >> 3) & 1) * 8) * 2;
    const uint32_t ks_base[2] = { smem_u32(Ks[0]), smem_u32(Ks[1]) };
    const uint32_t vs_base[2] = { smem_u32(Vs[0]), smem_u32(Vs[1]) };

    // Q fragments (half2 pairs), scaled by 0.125 (exact exponent shift)
    const __half2* Qh2 = (const __half2*)(Qb + ((size_t)h * T_DIM + it * 64) * HD);
    const __half2 qsc = __floats2half2_rn(0.125f, 0.125f);
    unsigned qf[4][4];
#pragma unroll
    for (int s = 0; s < 4; s++) {
        int r0 = (stripe + g) * 32, r1 = (stripe + g + 8) * 32;
        qf[s][0] = h2u(__hmul2(Qh2[r0 + s * 8 + tg], qsc));
        qf[s][1] = h2u(__hmul2(Qh2[r1 + s * 8 + tg], qsc));
        qf[s][2] = h2u(__hmul2(Qh2[r0 + s * 8 + tg + 4], qsc));
        qf[s][3] = h2u(__hmul2(Qh2[r1 + s * 8 + tg + 4], qsc));
    }

    float of[8][4];
#pragma unroll
    for (int nt = 0; nt < 8; nt++)
#pragma unroll
        for (int r = 0; r < 4; r++) of[nt][r] = 0.f;

    float m0 = -INFINITY, m1 = -INFINITY, l0 = 0.f, l1 = 0.f;

    const __half* Kh = Kb + (size_t)h * T_DIM * HD;
    const __half* Vh = Vb + (size_t)h * T_DIM * HD;

    const int vj = tid & 63;
    const int vc8 = tid >> 6;
    const int kj = tid >> 3, kc8 = tid & 7;

    // --- prologue: fill buffer 0 with tile 0 ---
    {
#pragma unroll
        for (int p = 0; p < 4; p++) {
            int j = kj + p * 16;
            CP_ASYNC16(smem_u32(&Ks[0][j * KPADH + kc8 * 8]),
                       Kh + (size_t)j * HD + kc8 * 8);
        }
        CP_COMMIT();
#pragma unroll
        for (int p = 0; p < 4; p++) {
            int c8 = vc8 + p * 2;
            uint4 vraw = *(const uint4*)(Vh + (size_t)vj * HD + c8 * 8);
            const __half* vh = (const __half*)&vraw;
#pragma unroll
            for (int q = 0; q < 8; q++)
                Vs[0][(c8 * 8 + q) * KPADH + vj] = vh[q];
        }
        asm volatile("cp.async.wait_group 0;" ::: "memory");
        __syncthreads();
    }

    for (int jt = 0; jt <= it; jt++) {
        const int buf = jt & 1;
        const bool diag = (jt == it);

        // --- prefetch next tile: K via cp.async, V into registers ---
        uint4 vpre[4];
        if (!diag) {
            const __half* Kn = Kh + (size_t)(jt + 1) * 64 * HD;
            const __half* Vn = Vh + (size_t)(jt + 1) * 64 * HD;
#pragma unroll
            for (int p = 0; p < 4; p++) {
                int j = kj + p * 16;
                CP_ASYNC16(smem_u32(&Ks[buf ^ 1][j * KPADH + kc8 * 8]),
                           Kn + (size_t)j * HD + kc8 * 8);
            }
            CP_COMMIT();
#pragma unroll
            for (int p = 0; p < 4; p++) {
                int c8 = vc8 + p * 2;
                vpre[p] = *(const uint4*)(Vn + (size_t)vj * HD + c8 * 8);
            }
        }

        // --- S = Q K^T (scaled); diag: trim to ntp < w+1 ---
        const int npmax = diag ? (w + 1) : 4;
        const int nmax = 2 * npmax;
        float sf[8][4];
#pragma unroll
        for (int nt = 0; nt < 8; nt++) {
            if (nt >= nmax) break;
            sf[nt][0] = sf[nt][1] = sf[nt][2] = sf[nt][3] = 0.f;
        }
#pragma unroll
        for (int s = 0; s < 4; s++) {
#pragma unroll
            for (int ntp = 0; ntp < 4; ntp++) {
                if (ntp >= npmax) break;
                unsigned bb[4];
                ldm_x4(bb, ks_base[buf] + bm_off[ntp] + s * 32);
                mma16(sf[2 * ntp],     qf[s], bb[0], bb[1]);
                mma16(sf[2 * ntp + 1], qf[s], bb[2], bb[3]);
            }
        }

        // --- causal mask on diagonal tile (registers) ---
        if (diag) {
            const int i0 = stripe + g, i1 = stripe + g + 8;
#pragma unroll
            for (int nt = 0; nt < 8; nt++) {
                if (nt >= nmax) break;
                int j0 = nt * 8 + 2 * tg;
                if (j0 > i0)     sf[nt][0] = -1e30f;
                if (j0 + 1 > i0) sf[nt][1] = -1e30f;
                if (j0 > i1)     sf[nt][2] = -1e30f;
                if (j0 + 1 > i1) sf[nt][3] = -1e30f;
            }
        }

        // --- row max via tg-quad shuffles ---
        float r0 = -INFINITY, r1 = -INFINITY;
#pragma unroll
        for (int nt = 0; nt < 8; nt++) {
            if (nt >= nmax) break;
            r0 = fmaxf(r0, fmaxf(sf[nt][0], sf[nt][1]));
            r1 = fmaxf(r1, fmaxf(sf[nt][2], sf[nt][3]));
        }
        r0 = fmaxf(r0, __shfl_xor_sync(0xffffffffu, r0, 1));
        r0 = fmaxf(r0, __shfl_xor_sync(0xffffffffu, r0, 2));
        r1 = fmaxf(r1, __shfl_xor_sync(0xffffffffu, r1, 1));
        r1 = fmaxf(r1, __shfl_xor_sync(0xffffffffu, r1, 2));

        const float mn0 = fmaxf(m0, r0), mn1 = fmaxf(m1, r1);
        const float c0 = __expf(m0 - mn0), c1 = __expf(m1 - mn1);

        // --- exp in registers, pack P fragments, partial sums ---
        float ps0 = 0.f, ps1 = 0.f;
        unsigned ph[8][2];
#pragma unroll
        for (int nt = 0; nt < 8; nt++) {
            if (nt >= nmax) break;
            float p0 = __expf(sf[nt][0] - mn0);
            float p1 = __expf(sf[nt][1] - mn0);
            float p2 = __expf(sf[nt][2] - mn1);
            float p3 = __expf(sf[nt][3] - mn1);
            ps0 += p0 + p1; ps1 += p2 + p3;
            ph[nt][0] = h2u(__floats2half2_rn(p0, p1));
            ph[nt][1] = h2u(__floats2half2_rn(p2, p3));
        }
        ps0 += __shfl_xor_sync(0xffffffffu, ps0, 1);
        ps0 += __shfl_xor_sync(0xffffffffu, ps0, 2);
        ps1 += __shfl_xor_sync(0xffffffffu, ps1, 1);
        ps1 += __shfl_xor_sync(0xffffffffu, ps1, 2);
        l0 = l0 * c0 + ps0; m0 = mn0;
        l1 = l1 * c1 + ps1; m1 = mn1;

        // --- rescale O, then O += P V (ldmatrix B-frags) ---
#pragma unroll
        for (int nt = 0; nt < 8; nt++) {
            of[nt][0] *= c0; of[nt][1] *= c0;
            of[nt][2] *= c1; of[nt][3] *= c1;
        }
        const int smax = diag ? (w + 1) : 4;
#pragma unroll
        for (int s = 0; s < 4; s++) {
            if (s >= smax) break;
            unsigned af[4] = { ph[2 * s][0], ph[2 * s][1], ph[2 * s + 1][0], ph[2 * s + 1][1] };
#pragma unroll
            for (int ntp = 0; ntp < 4; ntp++) {
                unsigned bb[4];
                ldm_x4(bb, vs_base[buf] + bm_off[ntp] + s * 32);
                mma16(of[2 * ntp],     af, bb[0], bb[1]);
                mma16(of[2 * ntp + 1], af, bb[2], bb[3]);
            }
        }

        // --- store prefetched V, close the pipeline stage ---
        if (!diag) {
#pragma unroll
            for (int p = 0; p < 4; p++) {
                int c8 = vc8 + p * 2;
                const __half* vh = (const __half*)&vpre[p];
#pragma unroll
                for (int q = 0; q < 8; q++)
                    Vs[buf ^ 1][(c8 * 8 + q) * KPADH + vj] = vh[q];
            }
            asm volatile("cp.async.wait_group 0;" ::: "memory");
            __syncthreads();
        }
    }

    // --- epilogue: O /= l, write [t][h*64+c] (f32) ---
    const float i0 = 1.f / l0, i1 = 1.f / l1;
    const int qi0 = it * 64 + stripe + g;
#pragma unroll
    for (int nt = 0; nt < 8; nt++) {
        int col = h * 64 + nt * 8 + 2 * tg;
        *(float2*)&vals[(size_t)qi0 * D_DIM + col] =
            make_float2(of[nt][0] * i0, of[nt][1] * i0);
        *(float2*)&vals[(size_t)(qi0 + 8) * D_DIM + col] =
            make_float2(of[nt][2] * i1, of[nt][3] * i1);
    }
}

// ---------------------------------------------------------------------------
extern "C" void kernel_launch(void* const* d_in, const int* in_sizes, int n_in,
                              void* d_out, int out_size)
{
    const float* q     = (const float*)d_in[0];
    const float* k     = (const float*)d_in[1];
    const float* v     = (const float*)d_in[2];
    // d_in[3] = mask (causal, static -> unused)
    const float* freqs = (const float*)d_in[4];
    const float* wq    = (const float*)d_in[5];
    const float* wk    = (const float*)d_in[6];
    const float* wv    = (const float*)d_in[7];
    const float* wo    = (const float*)d_in[8];
    float* out = (float*)d_out;

    __half *gq, *gk, *gv;
    float *gvals;
    cudaGetSymbolAddress((void**)&gq, g_Q);
    cudaGetSymbolAddress((void**)&gk, g_K);
    cudaGetSymbolAddress((void**)&gv, g_V);
    cudaGetSymbolAddress((void**)&gvals, g_vals);

    dim3 ggrid(D_DIM / 128, T_DIM / 128);  // (8, 32)

    gemm_f16<<<ggrid, 256>>>(q, wq, gq, T_DIM, D_DIM, D_DIM, 1);
    gemm_f16<<<ggrid, 256>>>(k, wk, gk, T_DIM, D_DIM, D_DIM, 1);
    gemm_f16<<<ggrid, 256>>>(v, wv, gv, T_DIM, D_DIM, D_DIM, 1);

    rope_kernel<<<dim3(NH * T_DIM * 16 / 256, 3), 256>>>(gq, gk, gv, freqs);

    attn_mma<<<dim3(T_DIM / 64, NH), 128>>>(gq, gk, gv, gvals);

    gemm_f16<<<ggrid, 256>>>(gvals, wo, out, T_DIM, D_DIM, D_DIM, 0);
}